// round 16
// baseline (speedup 1.0000x reference)
#include <cuda_runtime.h>
#include <cstdint>
#include <math.h>

// CropAndResize: x [B,H,W,C=4] fp32, boxes [B,4] (y1,x1,y2,x2 in [0,1]),
// output [B,crop,crop,4] fp32 bilinear.
//
// R15 vertical-pair direct-gather kernel with ONE change: output stores use
// __stcs (evict-first). The 25.7MB write stream is never re-read; with
// default policy it cycles through L2 competing with the read-reuse window
// (t+1-row and tr/tl overlap, which cuts read traffic 78MB -> 30MB).
// Evict-first keeps writes out of that working set.
// (Direct 4-corner gather retained: every redistribution scheme tested --
// LDS, cp.async, bulk-TMA, SHFL pair, SHFL quad -- lost on L1tex cycles.)

#define TPB 224

__global__ __launch_bounds__(TPB, 6)
void crop_resize_vpair_cs_kernel(const float* __restrict__ x,
                                 const float* __restrict__ boxes,
                                 float* __restrict__ out,
                                 int H, int W, int crop) {
    const int r0 = blockIdx.x * 2;       // first output row (uniform)
    const int r1 = r0 + 1;
    const int b  = blockIdx.y;           // batch (uniform)

    const float4 bx = __ldg((const float4*)boxes + b);   // y1,x1,y2,x2
    const float inv = 1.0f / (float)(crop - 1);
    const float hm1 = (float)(H - 1);
    const float wm1 = (float)(W - 1);

    // ---- block-uniform vertical math for both rows ----
    const float yoff = bx.x * hm1;
    const float yscl = inv * (bx.z - bx.x) * hm1;       // >= 0

    const float in_y0 = fmaf((float)r0, yscl, yoff);
    const float in_y1 = fmaf((float)r1, yscl, yoff);
    const bool vy0 = (in_y0 >= 0.0f) && (in_y0 <= hm1);
    const bool vy1 = (in_y1 >= 0.0f) && (in_y1 <= hm1);
    const int t0 = min(max((int)in_y0, 0), H - 2);
    const int t1 = min(max((int)in_y1, 0), H - 2);
    const float yl0 = in_y0 - (float)t0;
    const float yl1 = in_y1 - (float)t1;

    const float4* __restrict__ xb = (const float4*)(x) + (size_t)b * H * W;
    const float4* __restrict__ rowA = xb + (size_t)t0 * W;
    const float4* __restrict__ rowB = xb + (size_t)t1 * W;

    float4* __restrict__ outr0 = (float4*)(out) + ((size_t)b * crop + r0) * crop;
    float4* __restrict__ outr1 = (float4*)(out) + ((size_t)b * crop + r1) * crop;

    const float xoff = bx.y * wm1;
    const float xscl = inv * (bx.w - bx.y) * wm1;       // >= 0

    const bool has_r1 = (r1 < crop);                    // uniform

    for (int c = threadIdx.x; c < crop; c += TPB) {
        const float in_x = fmaf((float)c, xscl, xoff);
        const bool vx = (in_x >= 0.0f) && (in_x <= wm1);

        const int l = min(max((int)in_x, 0), W - 2);
        const float xl = in_x - (float)l;

        // 8 independent gathers, issued before any consumption (MLP=8)
        const float4 a_tl = __ldg(rowA + l);
        const float4 a_tr = __ldg(rowA + l + 1);
        const float4 a_bl = __ldg(rowA + l + W);
        const float4 a_br = __ldg(rowA + l + W + 1);
        const float4 b_tl = __ldg(rowB + l);
        const float4 b_tr = __ldg(rowB + l + 1);
        const float4 b_bl = __ldg(rowB + l + W);
        const float4 b_br = __ldg(rowB + l + W + 1);

        // row r0
        {
            float4 res = make_float4(0.f, 0.f, 0.f, 0.f);
            if (vx && vy0) {
                const float tx = fmaf(a_tr.x - a_tl.x, xl, a_tl.x);
                const float ty = fmaf(a_tr.y - a_tl.y, xl, a_tl.y);
                const float tz = fmaf(a_tr.z - a_tl.z, xl, a_tl.z);
                const float tw = fmaf(a_tr.w - a_tl.w, xl, a_tl.w);
                const float ux = fmaf(a_br.x - a_bl.x, xl, a_bl.x);
                const float uy = fmaf(a_br.y - a_bl.y, xl, a_bl.y);
                const float uz = fmaf(a_br.z - a_bl.z, xl, a_bl.z);
                const float uw = fmaf(a_br.w - a_bl.w, xl, a_bl.w);
                res.x = fmaf(ux - tx, yl0, tx);
                res.y = fmaf(uy - ty, yl0, ty);
                res.z = fmaf(uz - tz, yl0, tz);
                res.w = fmaf(uw - tw, yl0, tw);
            }
            __stcs(outr0 + c, res);
        }

        // row r1
        if (has_r1) {
            float4 res = make_float4(0.f, 0.f, 0.f, 0.f);
            if (vx && vy1) {
                const float tx = fmaf(b_tr.x - b_tl.x, xl, b_tl.x);
                const float ty = fmaf(b_tr.y - b_tl.y, xl, b_tl.y);
                const float tz = fmaf(b_tr.z - b_tl.z, xl, b_tl.z);
                const float tw = fmaf(b_tr.w - b_tl.w, xl, b_tl.w);
                const float ux = fmaf(b_br.x - b_bl.x, xl, b_bl.x);
                const float uy = fmaf(b_br.y - b_bl.y, xl, b_bl.y);
                const float uz = fmaf(b_br.z - b_bl.z, xl, b_bl.z);
                const float uw = fmaf(b_br.w - b_bl.w, xl, b_bl.w);
                res.x = fmaf(ux - tx, yl1, tx);
                res.y = fmaf(uy - ty, yl1, ty);
                res.z = fmaf(uz - tz, yl1, tz);
                res.w = fmaf(uw - tw, yl1, tw);
            }
            __stcs(outr1 + c, res);
        }
    }
}

extern "C" void kernel_launch(void* const* d_in, const int* in_sizes, int n_in,
                              void* d_out, int out_size) {
    const float* x     = (const float*)d_in[0];
    const float* boxes = (const float*)d_in[1];
    float* out = (float*)d_out;

    const int B = in_sizes[1] / 4;          // boxes is [B,4]
    const int C = 4;
    const long long hw = (long long)in_sizes[0] / ((long long)B * C);
    int H = (int)(sqrt((double)hw) + 0.5);
    int W = H;
    const long long cc = (long long)out_size / ((long long)B * C);
    int crop = (int)(sqrt((double)cc) + 0.5);

    dim3 grid((crop + 1) / 2, B);
    crop_resize_vpair_cs_kernel<<<grid, TPB>>>(x, boxes, out, H, W, crop);
}

// round 17
// speedup vs baseline: 1.0021x; 1.0021x over previous
#include <cuda_runtime.h>
#include <cstdint>
#include <math.h>

// CropAndResize: x [B,H,W,C=4] fp32, boxes [B,4] (y1,x1,y2,x2 in [0,1]),
// output [B,crop,crop,4] fp32 bilinear.
//
// Final form: the R1 direct 4-corner-gather pattern (best measured across
// 16 rounds; every alternative -- LDS/cp.async/bulk-TMA staging, SHFL
// pair/quad packing, separable smem, vertical pairing, cache-policy hints,
// uniform-pipe offload -- tied or regressed). One pixel per thread,
// 4 corner float4 gathers with max in-flight overlap, coalesced STG.128.
// This round's single variable: 128-thread blocks (16/SM) to smooth wave
// ramp/drain and close the achieved-vs-theoretical occupancy gap
// (79.5% -> ~88%), the only meter gap not yet attacked.

#define TPB 128

__global__ __launch_bounds__(TPB)
void crop_resize_final_kernel(const float* __restrict__ x,
                              const float* __restrict__ boxes,
                              float* __restrict__ out,
                              int H, int W, int crop) {
    const int b   = blockIdx.y;
    const int idx = blockIdx.x * TPB + threadIdx.x;
    const int npx = crop * crop;
    if (idx >= npx) return;

    const int row = idx / crop;
    const int col = idx - row * crop;

    const float4 bx = __ldg((const float4*)boxes + b);   // y1,x1,y2,x2

    const float inv = 1.0f / (float)(crop - 1);
    const float hm1 = (float)(H - 1);
    const float wm1 = (float)(W - 1);

    const float in_y = (bx.x + (float)row * inv * (bx.z - bx.x)) * hm1;
    const float in_x = (bx.y + (float)col * inv * (bx.w - bx.y)) * wm1;

    const bool valid = (in_y >= 0.0f) && (in_y <= hm1) &&
                       (in_x >= 0.0f) && (in_x <= wm1);

    // clamp form t in [0,H-2], yl = in_y - t (validated vs reference R8-R16)
    const int t = min(max((int)in_y, 0), H - 2);
    const int l = min(max((int)in_x, 0), W - 2);
    const float yl = in_y - (float)t;
    const float xl = in_x - (float)l;

    const float4* __restrict__ p =
        (const float4*)(x) + ((size_t)b * H + t) * W + l;

    // 4 independent gathers issued back-to-back
    const float4 tl4 = __ldg(p);
    const float4 tr4 = __ldg(p + 1);
    const float4 bl4 = __ldg(p + W);
    const float4 br4 = __ldg(p + W + 1);

    float4 res = make_float4(0.f, 0.f, 0.f, 0.f);
    if (valid) {
        const float tx = fmaf(tr4.x - tl4.x, xl, tl4.x);
        const float ty = fmaf(tr4.y - tl4.y, xl, tl4.y);
        const float tz = fmaf(tr4.z - tl4.z, xl, tl4.z);
        const float tw = fmaf(tr4.w - tl4.w, xl, tl4.w);
        const float ux = fmaf(br4.x - bl4.x, xl, bl4.x);
        const float uy = fmaf(br4.y - bl4.y, xl, bl4.y);
        const float uz = fmaf(br4.z - bl4.z, xl, bl4.z);
        const float uw = fmaf(br4.w - bl4.w, xl, bl4.w);
        res.x = fmaf(ux - tx, yl, tx);
        res.y = fmaf(uy - ty, yl, ty);
        res.z = fmaf(uz - tz, yl, tz);
        res.w = fmaf(uw - tw, yl, tw);
    }

    float4* __restrict__ outb = (float4*)(out) + (size_t)b * npx;
    outb[idx] = res;
}

extern "C" void kernel_launch(void* const* d_in, const int* in_sizes, int n_in,
                              void* d_out, int out_size) {
    const float* x     = (const float*)d_in[0];
    const float* boxes = (const float*)d_in[1];
    float* out = (float*)d_out;

    const int B = in_sizes[1] / 4;          // boxes is [B,4]
    const int C = 4;
    const long long hw = (long long)in_sizes[0] / ((long long)B * C);
    int H = (int)(sqrt((double)hw) + 0.5);
    int W = H;
    const long long cc = (long long)out_size / ((long long)B * C);
    int crop = (int)(sqrt((double)cc) + 0.5);

    const int npx = crop * crop;
    dim3 grid((npx + TPB - 1) / TPB, B);
    crop_resize_final_kernel<<<grid, TPB>>>(x, boxes, out, H, W, crop);
}